// round 16
// baseline (speedup 1.0000x reference)
#include <cuda_runtime.h>
#include <math.h>

// ---------------- problem constants ----------------
#define T_STEPS 64
#define B_SZ    128
#define M_COLS  1000
#define N_CELLS 4
#define TC      4000      // M_COLS * N_CELLS
#define K_TOP   25
#define D_IN    1024
#define D_OUT   1024
#define GEMM_BLOCKS 512   // 64 timesteps x 8 column tiles

// ---------------- persistent device state ----------------
__device__ float g_za_all[T_STEPS * B_SZ * M_COLS]; // feedforward drive
__device__ float g_wbt  [TC * TC];                  // w_b transposed
__device__ float g_wdt  [M_COLS * D_OUT];           // w_d transposed
__device__ int   g_cnt  [T_STEPS];                  // za readiness counters

// ---------------- init (counters must reset every graph replay) ----------------
__global__ void zero_cnt_kernel() {
    if (threadIdx.x < T_STEPS) g_cnt[threadIdx.x] = 0;
}

// ---------------- generic 32x32 tiled transpose with bounds ----------------
__global__ void transpose_kernel(const float* __restrict__ in, float* __restrict__ out,
                                 int rows, int cols)
{
    __shared__ float tile[32][33];
    int c0 = blockIdx.x * 32, r0 = blockIdx.y * 32;
#pragma unroll
    for (int j = 0; j < 32; j += 8) {
        int r = r0 + threadIdx.y + j, c = c0 + threadIdx.x;
        if (r < rows && c < cols)
            tile[threadIdx.y + j][threadIdx.x] = in[(size_t)r * cols + c];
    }
    __syncthreads();
#pragma unroll
    for (int j = 0; j < 32; j += 8) {
        int c = c0 + threadIdx.y + j, r = r0 + threadIdx.x;
        if (r < rows && c < cols)
            out[(size_t)c * rows + r] = tile[threadIdx.x][threadIdx.y + j];
    }
}

// ---------------- helpers ----------------
// lane-local tree max over 32 register values; ties -> smaller j
__device__ __forceinline__ void tree_max32(const float v[32], float& bv, int& bj)
{
    float tv[16]; int tj[16];
#pragma unroll
    for (int j = 0; j < 16; j++) {
        bool t = v[2 * j + 1] > v[2 * j];
        tv[j] = t ? v[2 * j + 1] : v[2 * j];
        tj[j] = t ? 2 * j + 1 : 2 * j;
    }
#pragma unroll
    for (int s = 8; s >= 1; s >>= 1) {
#pragma unroll
        for (int j = 0; j < s; j++) {
            bool t = tv[j + s] > tv[j];
            tv[j] = t ? tv[j + s] : tv[j];
            tj[j] = t ? tj[j + s] : tj[j];
        }
    }
    bv = tv[0]; bj = tj[0];
}

// ---------------- shared memory overlays ----------------
struct GemmSmem {                       // 34,304 B
    float As[2][16][128 + 4];
    float Bs[2][16][128 + 8];
};
struct ScanSmem {                       // ~29.5 KB
    float         psi[TC];
    float         lam[M_COLS];
    float         sig[M_COLS];
    unsigned char win[M_COLS];
    int           didx [K_TOP];
    float         delta[K_TOP];
    int           ycol [K_TOP];         // winner columns (for decode)
    float         yval [K_TOP];         // max(y,0) (for decode)
};

// ---------------- GEMM part: one 128x128 za tile, then signal ----------------
__device__ void gemm_part(const float* __restrict__ x, const float* __restrict__ w_a,
                          char* smem, int gbid)
{
    GemmSmem* S = reinterpret_cast<GemmSmem*>(smem);
    const int t   = gbid >> 3;
    const int n0  = (gbid & 7) * 128;
    const int tid = threadIdx.x;
    const int tn  = tid & 31;
    const int tm  = tid >> 5;
    const int arow = tid >> 2, aq = tid & 3;

    const float* A = x + (size_t)t * B_SZ * D_IN;
    float*       C = g_za_all + (size_t)t * B_SZ * M_COLS;

    unsigned long long acc[8][2];
#pragma unroll
    for (int i = 0; i < 8; i++) { acc[i][0] = 0ull; acc[i][1] = 0ull; }

    float4 aR = *reinterpret_cast<const float4*>(&A[(size_t)arow * D_IN + aq * 4]);
    float4 bR = make_float4(0.f, 0.f, 0.f, 0.f);
    if (n0 + arow < M_COLS)
        bR = *reinterpret_cast<const float4*>(&w_a[(size_t)(n0 + arow) * D_IN + aq * 4]);
    {
        S->As[0][aq * 4 + 0][arow] = aR.x; S->As[0][aq * 4 + 1][arow] = aR.y;
        S->As[0][aq * 4 + 2][arow] = aR.z; S->As[0][aq * 4 + 3][arow] = aR.w;
        S->Bs[0][aq * 4 + 0][arow] = bR.x; S->Bs[0][aq * 4 + 1][arow] = bR.y;
        S->Bs[0][aq * 4 + 2][arow] = bR.z; S->Bs[0][aq * 4 + 3][arow] = bR.w;
    }
    __syncthreads();

    const int nk = D_IN / 16;
    for (int kt = 0; kt < nk; kt++) {
        const int buf = kt & 1;
        if (kt + 1 < nk) {
            int kb = (kt + 1) * 16;
            aR = *reinterpret_cast<const float4*>(&A[(size_t)arow * D_IN + kb + aq * 4]);
            bR = make_float4(0.f, 0.f, 0.f, 0.f);
            if (n0 + arow < M_COLS)
                bR = *reinterpret_cast<const float4*>(&w_a[(size_t)(n0 + arow) * D_IN + kb + aq * 4]);
        }
#pragma unroll
        for (int k = 0; k < 16; k++) {
            float4 a0 = *reinterpret_cast<const float4*>(&S->As[buf][k][tm * 8]);
            float4 a1 = *reinterpret_cast<const float4*>(&S->As[buf][k][tm * 8 + 4]);
            const unsigned long long* bp =
                reinterpret_cast<const unsigned long long*>(&S->Bs[buf][k][tn * 4]);
            unsigned long long b2[2] = {bp[0], bp[1]};
            float av[8] = {a0.x, a0.y, a0.z, a0.w, a1.x, a1.y, a1.z, a1.w};
#pragma unroll
            for (int i = 0; i < 8; i++) {
                unsigned int au = __float_as_uint(av[i]);
                unsigned long long ap;
                asm("mov.b64 %0, {%1, %1};" : "=l"(ap) : "r"(au));
                asm("fma.rn.f32x2 %0, %1, %2, %0;" : "+l"(acc[i][0]) : "l"(ap), "l"(b2[0]));
                asm("fma.rn.f32x2 %0, %1, %2, %0;" : "+l"(acc[i][1]) : "l"(ap), "l"(b2[1]));
            }
        }
        if (kt + 1 < nk) {
            const int nb = buf ^ 1;
            S->As[nb][aq * 4 + 0][arow] = aR.x; S->As[nb][aq * 4 + 1][arow] = aR.y;
            S->As[nb][aq * 4 + 2][arow] = aR.z; S->As[nb][aq * 4 + 3][arow] = aR.w;
            S->Bs[nb][aq * 4 + 0][arow] = bR.x; S->Bs[nb][aq * 4 + 1][arow] = bR.y;
            S->Bs[nb][aq * 4 + 2][arow] = bR.z; S->Bs[nb][aq * 4 + 3][arow] = bR.w;
            __syncthreads();
        }
    }

#pragma unroll
    for (int i = 0; i < 8; i++) {
        int gm = tm * 8 + i;
#pragma unroll
        for (int j = 0; j < 2; j++) {
            unsigned int lo, hi;
            asm("mov.b64 {%0, %1}, %2;" : "=r"(lo), "=r"(hi) : "l"(acc[i][j]));
            int gn = n0 + tn * 4 + 2 * j;
            if (gn < M_COLS)     C[(size_t)gm * M_COLS + gn]     = __uint_as_float(lo);
            if (gn + 1 < M_COLS) C[(size_t)gm * M_COLS + gn + 1] = __uint_as_float(hi);
        }
    }

    __threadfence();
    __syncthreads();
    if (threadIdx.x == 0) atomicAdd(&g_cnt[t], 1);
}

// ---------------- scan part: R9 structure + inline decode ----------------
__device__ void scan_part(char* smem, int b,
                          const float* __restrict__ b_d, float* __restrict__ out)
{
    ScanSmem* S = reinterpret_cast<ScanSmem*>(smem);
    const int tid    = threadIdx.x;
    const int lane   = tid & 31;
    const int warpid = tid >> 5;

    const int c0 = tid;                // column 0..511
    const int c1 = tid + 512;          // column 512..1023 (valid < 1000)
    const bool two = (c1 < M_COLS);
    const int d0 = tid * 2;            // this thread's 2 output dims

    float4 z0 = make_float4(0.f, 0.f, 0.f, 0.f);
    float4 z1 = make_float4(0.f, 0.f, 0.f, 0.f);

    const float2 bias = *reinterpret_cast<const float2*>(&b_d[d0]);

    for (int i = tid; i < TC; i += 512) S->psi[i] = 0.f;
    __syncthreads();

    for (int t = 0; t < T_STEPS; t++) {
        // wait for za[t] (8 tiles)
        if (tid == 0) {
            unsigned int v;
            do {
                asm volatile("ld.acquire.gpu.u32 %0, [%1];"
                             : "=r"(v) : "l"(&g_cnt[t]) : "memory");
            } while (v < 8u);
        }
        __syncthreads();

        // ---- fused (t>0): rank-25 z_b update + decode of row (t-1,b) ----
        if (t > 0) {
            float4 a0 = make_float4(0.5f * z0.x, 0.5f * z0.y, 0.5f * z0.z, 0.5f * z0.w);
            float4 a1 = make_float4(0.5f * z1.x, 0.5f * z1.y, 0.5f * z1.z, 0.5f * z1.w);
            float2 dec = bias;
#pragma unroll
            for (int i = 0; i < K_TOP; i++) {
                float d = S->delta[i];
                const float* base = &g_wbt[(size_t)S->didx[i] * TC];
                float4 w0 = *reinterpret_cast<const float4*>(&base[c0 * 4]);
                a0.x = fmaf(d, w0.x, a0.x); a0.y = fmaf(d, w0.y, a0.y);
                a0.z = fmaf(d, w0.z, a0.z); a0.w = fmaf(d, w0.w, a0.w);
                if (two) {
                    float4 w1 = *reinterpret_cast<const float4*>(&base[c1 * 4]);
                    a1.x = fmaf(d, w1.x, a1.x); a1.y = fmaf(d, w1.y, a1.y);
                    a1.z = fmaf(d, w1.z, a1.z); a1.w = fmaf(d, w1.w, a1.w);
                }
                float yv = S->yval[i];
                const float2 wd = *reinterpret_cast<const float2*>(
                    &g_wdt[(size_t)S->ycol[i] * D_OUT + d0]);
                dec.x = fmaf(yv, wd.x, dec.x);
                dec.y = fmaf(yv, wd.y, dec.y);
            }
            z0 = a0; z1 = a1;
            *reinterpret_cast<float2*>(
                &out[((size_t)(t - 1) * B_SZ + b) * D_OUT + d0]) = dec;
        }

        // ---- phase A: winner cell + column max of pi + psi decay ----
        const float* zab = g_za_all + ((size_t)t * B_SZ + b) * M_COLS;
#pragma unroll
        for (int h = 0; h < 2; h++) {
            int c = (h == 0) ? c0 : c1;
            if (h == 1 && !two) break;
            float4 z = (h == 0) ? z0 : z1;
            float  zac = __ldcg(&zab[c]);
            float4 ph  = *reinterpret_cast<const float4*>(&S->psi[c * 4]);
            float sig[4] = {zac + z.x, zac + z.y, zac + z.z, zac + z.w};
            float pv [4] = {sig[0] * (1.f - ph.x), sig[1] * (1.f - ph.y),
                            sig[2] * (1.f - ph.z), sig[3] * (1.f - ph.w)};
            float best = pv[0]; int bw = 0;
#pragma unroll
            for (int n = 1; n < N_CELLS; n++)
                if (pv[n] > best) { best = pv[n]; bw = n; }
            S->lam[c] = best;
            S->win[c] = (unsigned char)bw;
            S->sig[c] = sig[bw];
            *reinterpret_cast<float4*>(&S->psi[c * 4]) =
                make_float4(0.5f * ph.x, 0.5f * ph.y, 0.5f * ph.z, 0.5f * ph.w);
        }
        __syncthreads();

        // ---- top-K by warp 0 (R9 butterfly + tree rescan) ----
        if (warpid == 0) {
            float v[32];
#pragma unroll
            for (int j = 0; j < 32; j++) {
                int c = j * 32 + lane;
                v[j] = (c < M_COLS) ? S->lam[c] : -INFINITY;
            }
            float lv; int lj;
            tree_max32(v, lv, lj);
            int mycol = 0;

            for (int it = 0; it < K_TOP; it++) {
                float bv = lv;
                int   bc = lj * 32 + lane;
#pragma unroll
                for (int off = 16; off > 0; off >>= 1) {
                    float ov = __shfl_xor_sync(0xffffffffu, bv, off);
                    int   oc = __shfl_xor_sync(0xffffffffu, bc, off);
                    if (ov > bv || (ov == bv && oc < bc)) { bv = ov; bc = oc; }
                }
                if (lane == it) mycol = bc;
                if ((bc & 31) == lane) {
                    v[bc >> 5] = -INFINITY;
                    tree_max32(v, lv, lj);
                }
            }
            __syncwarp();

            // ---- emit: lanes 0..24, one winner each (psi already decayed) ----
            if (lane < K_TOP) {
                int   c    = mycol;
                int   w    = (int)S->win[c];
                int   cell = c * N_CELLS + w;
                float y    = tanhf(S->sig[c]);
                float pd   = S->psi[cell];
                S->didx [lane] = cell;
                S->delta[lane] = fmaxf(y - pd, 0.f);
                S->psi[cell]   = fmaxf(pd, y);
                S->ycol [lane] = c;
                S->yval [lane] = fmaxf(y, 0.f);
            }
        }
        __syncthreads();
    }

    // ---- final decode for row (T_STEPS-1, b) ----
    {
        float2 dec = bias;
#pragma unroll
        for (int i = 0; i < K_TOP; i++) {
            float yv = S->yval[i];
            const float2 wd = *reinterpret_cast<const float2*>(
                &g_wdt[(size_t)S->ycol[i] * D_OUT + d0]);
            dec.x = fmaf(yv, wd.x, dec.x);
            dec.y = fmaf(yv, wd.y, dec.y);
        }
        *reinterpret_cast<float2*>(
            &out[((size_t)(T_STEPS - 1) * B_SZ + b) * D_OUT + d0]) = dec;
    }
}

// ---------------- fused GEMM + scan kernel (scan blocks FIRST) ----------------
__global__ void __launch_bounds__(512, 2)
fused_gemm_scan(const float* __restrict__ x, const float* __restrict__ w_a,
                const float* __restrict__ b_d, float* __restrict__ out)
{
    __shared__ __align__(16) char smem[sizeof(GemmSmem)];
    if (blockIdx.x < B_SZ) scan_part(smem, blockIdx.x, b_d, out);
    else                   gemm_part(x, w_a, smem, blockIdx.x - B_SZ);
}

// ---------------- host launch ----------------
extern "C" void kernel_launch(void* const* d_in, const int* in_sizes, int n_in,
                              void* d_out, int out_size)
{
    const float* x   = (const float*)d_in[0];   // [T, B, D_IN]
    const float* w_a = (const float*)d_in[1];   // [M, D_IN]
    const float* w_b = (const float*)d_in[2];   // [TC, TC]
    const float* w_d = (const float*)d_in[3];   // [D_OUT, M]
    const float* b_d = (const float*)d_in[4];   // [D_OUT]
    float* out = (float*)d_out;                 // [T, B, D_OUT]

    float *wbt, *wdt;
    cudaGetSymbolAddress((void**)&wbt, g_wbt);
    cudaGetSymbolAddress((void**)&wdt, g_wdt);

    zero_cnt_kernel<<<1, 64>>>();

    transpose_kernel<<<dim3(TC / 32, TC / 32), dim3(32, 8)>>>(w_b, wbt, TC, TC);
    transpose_kernel<<<dim3((M_COLS + 31) / 32, D_OUT / 32), dim3(32, 8)>>>(
        w_d, wdt, D_OUT, M_COLS);

    fused_gemm_scan<<<B_SZ + GEMM_BLOCKS, 512>>>(x, w_a, b_d, out);
}

// round 17
// speedup vs baseline: 1.0096x; 1.0096x over previous
#include <cuda_runtime.h>
#include <math.h>

// ---------------- problem constants ----------------
#define T_STEPS 64
#define B_SZ    128
#define M_COLS  1000
#define N_CELLS 4
#define TC      4000      // M_COLS * N_CELLS
#define K_TOP   25
#define D_IN    1024
#define D_OUT   1024
#define GEMM_BLOCKS 512   // 64 timesteps x 8 column tiles

// ---------------- persistent device state ----------------
__device__ float g_za_all[T_STEPS * B_SZ * M_COLS]; // feedforward drive
__device__ float g_wbt  [TC * TC];                  // w_b transposed
__device__ float g_wdt  [M_COLS * D_OUT];           // w_d transposed
__device__ int   g_ycidx[T_STEPS * B_SZ * K_TOP];   // selected columns per (t,b)
__device__ float g_ycval[T_STEPS * B_SZ * K_TOP];   // max(y,0) per (t,b)
__device__ int   g_cnt  [T_STEPS];                  // za readiness counters

// ---------------- init (counters must reset every graph replay) ----------------
__global__ void zero_cnt_kernel() {
    if (threadIdx.x < T_STEPS) g_cnt[threadIdx.x] = 0;
}

// ---------------- generic 32x32 tiled transpose with bounds ----------------
__global__ void transpose_kernel(const float* __restrict__ in, float* __restrict__ out,
                                 int rows, int cols)
{
    __shared__ float tile[32][33];
    int c0 = blockIdx.x * 32, r0 = blockIdx.y * 32;
#pragma unroll
    for (int j = 0; j < 32; j += 8) {
        int r = r0 + threadIdx.y + j, c = c0 + threadIdx.x;
        if (r < rows && c < cols)
            tile[threadIdx.y + j][threadIdx.x] = in[(size_t)r * cols + c];
    }
    __syncthreads();
#pragma unroll
    for (int j = 0; j < 32; j += 8) {
        int c = c0 + threadIdx.y + j, r = r0 + threadIdx.x;
        if (r < rows && c < cols)
            out[(size_t)c * rows + r] = tile[threadIdx.x][threadIdx.y + j];
    }
}

// ---------------- helpers ----------------
// lane-local tree max over 32 register values; ties -> smaller j
__device__ __forceinline__ void tree_max32(const float v[32], float& bv, int& bj)
{
    float tv[16]; int tj[16];
#pragma unroll
    for (int j = 0; j < 16; j++) {
        bool t = v[2 * j + 1] > v[2 * j];
        tv[j] = t ? v[2 * j + 1] : v[2 * j];
        tj[j] = t ? 2 * j + 1 : 2 * j;
    }
#pragma unroll
    for (int s = 8; s >= 1; s >>= 1) {
#pragma unroll
        for (int j = 0; j < s; j++) {
            bool t = tv[j + s] > tv[j];
            tv[j] = t ? tv[j + s] : tv[j];
            tj[j] = t ? tj[j + s] : tj[j];
        }
    }
    bv = tv[0]; bj = tj[0];
}

// ---------------- shared memory overlays ----------------
struct GemmSmem {                       // 34,304 B
    float As[2][16][128 + 4];
    float Bs[2][16][128 + 8];
};
struct ScanSmem {                       // ~29.2 KB
    float         psi[TC];
    float         lam[M_COLS];
    float         sig[M_COLS];
    unsigned char win[M_COLS];
    int           didx [K_TOP];
    float         delta[K_TOP];
};

// ---------------- GEMM part: one 128x128 za tile, then signal ----------------
__device__ void gemm_part(const float* __restrict__ x, const float* __restrict__ w_a,
                          char* smem, int gbid)
{
    GemmSmem* S = reinterpret_cast<GemmSmem*>(smem);
    const int t   = gbid >> 3;
    const int n0  = (gbid & 7) * 128;
    const int tid = threadIdx.x;
    const int tn  = tid & 31;
    const int tm  = tid >> 5;
    const int arow = tid >> 2, aq = tid & 3;

    const float* A = x + (size_t)t * B_SZ * D_IN;
    float*       C = g_za_all + (size_t)t * B_SZ * M_COLS;

    unsigned long long acc[8][2];
#pragma unroll
    for (int i = 0; i < 8; i++) { acc[i][0] = 0ull; acc[i][1] = 0ull; }

    float4 aR = *reinterpret_cast<const float4*>(&A[(size_t)arow * D_IN + aq * 4]);
    float4 bR = make_float4(0.f, 0.f, 0.f, 0.f);
    if (n0 + arow < M_COLS)
        bR = *reinterpret_cast<const float4*>(&w_a[(size_t)(n0 + arow) * D_IN + aq * 4]);
    {
        S->As[0][aq * 4 + 0][arow] = aR.x; S->As[0][aq * 4 + 1][arow] = aR.y;
        S->As[0][aq * 4 + 2][arow] = aR.z; S->As[0][aq * 4 + 3][arow] = aR.w;
        S->Bs[0][aq * 4 + 0][arow] = bR.x; S->Bs[0][aq * 4 + 1][arow] = bR.y;
        S->Bs[0][aq * 4 + 2][arow] = bR.z; S->Bs[0][aq * 4 + 3][arow] = bR.w;
    }
    __syncthreads();

    const int nk = D_IN / 16;
    for (int kt = 0; kt < nk; kt++) {
        const int buf = kt & 1;
        if (kt + 1 < nk) {
            int kb = (kt + 1) * 16;
            aR = *reinterpret_cast<const float4*>(&A[(size_t)arow * D_IN + kb + aq * 4]);
            bR = make_float4(0.f, 0.f, 0.f, 0.f);
            if (n0 + arow < M_COLS)
                bR = *reinterpret_cast<const float4*>(&w_a[(size_t)(n0 + arow) * D_IN + kb + aq * 4]);
        }
#pragma unroll
        for (int k = 0; k < 16; k++) {
            float4 a0 = *reinterpret_cast<const float4*>(&S->As[buf][k][tm * 8]);
            float4 a1 = *reinterpret_cast<const float4*>(&S->As[buf][k][tm * 8 + 4]);
            const unsigned long long* bp =
                reinterpret_cast<const unsigned long long*>(&S->Bs[buf][k][tn * 4]);
            unsigned long long b2[2] = {bp[0], bp[1]};
            float av[8] = {a0.x, a0.y, a0.z, a0.w, a1.x, a1.y, a1.z, a1.w};
#pragma unroll
            for (int i = 0; i < 8; i++) {
                unsigned int au = __float_as_uint(av[i]);
                unsigned long long ap;
                asm("mov.b64 %0, {%1, %1};" : "=l"(ap) : "r"(au));
                asm("fma.rn.f32x2 %0, %1, %2, %0;" : "+l"(acc[i][0]) : "l"(ap), "l"(b2[0]));
                asm("fma.rn.f32x2 %0, %1, %2, %0;" : "+l"(acc[i][1]) : "l"(ap), "l"(b2[1]));
            }
        }
        if (kt + 1 < nk) {
            const int nb = buf ^ 1;
            S->As[nb][aq * 4 + 0][arow] = aR.x; S->As[nb][aq * 4 + 1][arow] = aR.y;
            S->As[nb][aq * 4 + 2][arow] = aR.z; S->As[nb][aq * 4 + 3][arow] = aR.w;
            S->Bs[nb][aq * 4 + 0][arow] = bR.x; S->Bs[nb][aq * 4 + 1][arow] = bR.y;
            S->Bs[nb][aq * 4 + 2][arow] = bR.z; S->Bs[nb][aq * 4 + 3][arow] = bR.w;
            __syncthreads();
        }
    }

#pragma unroll
    for (int i = 0; i < 8; i++) {
        int gm = tm * 8 + i;
#pragma unroll
        for (int j = 0; j < 2; j++) {
            unsigned int lo, hi;
            asm("mov.b64 {%0, %1}, %2;" : "=r"(lo), "=r"(hi) : "l"(acc[i][j]));
            int gn = n0 + tn * 4 + 2 * j;
            if (gn < M_COLS)     C[(size_t)gm * M_COLS + gn]     = __uint_as_float(lo);
            if (gn + 1 < M_COLS) C[(size_t)gm * M_COLS + gn + 1] = __uint_as_float(hi);
        }
    }

    __threadfence();
    __syncthreads();
    if (threadIdx.x == 0) atomicAdd(&g_cnt[t], 1);
}

// ---------------- scan part: R9 structure + za prefetch hoist ----------------
__device__ void scan_part(char* smem, int b)
{
    ScanSmem* S = reinterpret_cast<ScanSmem*>(smem);
    const int tid    = threadIdx.x;
    const int lane   = tid & 31;
    const int warpid = tid >> 5;

    const int c0 = tid;                // column 0..511
    const int c1 = tid + 512;          // column 512..1023 (valid < 1000)
    const bool two = (c1 < M_COLS);

    float4 z0 = make_float4(0.f, 0.f, 0.f, 0.f);
    float4 z1 = make_float4(0.f, 0.f, 0.f, 0.f);

    for (int i = tid; i < TC; i += 512) S->psi[i] = 0.f;
    __syncthreads();

    for (int t = 0; t < T_STEPS; t++) {
        // wait for za[t] (8 tiles)
        if (tid == 0) {
            unsigned int v;
            do {
                asm volatile("ld.acquire.gpu.u32 %0, [%1];"
                             : "=r"(v) : "l"(&g_cnt[t]) : "memory");
            } while (v < 8u);
        }
        __syncthreads();

        // ---- PREFETCH za[t] now so it overlaps the rank-25 gather below ----
        const float* zab = g_za_all + ((size_t)t * B_SZ + b) * M_COLS;
        float zac0 = __ldcg(&zab[c0]);
        float zac1 = two ? __ldcg(&zab[c1]) : 0.f;

        // ---- fused: rank-25 z_b update (t>0), fully unrolled (high MLP) ----
        if (t > 0) {
            float4 a0 = make_float4(0.5f * z0.x, 0.5f * z0.y, 0.5f * z0.z, 0.5f * z0.w);
            float4 a1 = make_float4(0.5f * z1.x, 0.5f * z1.y, 0.5f * z1.z, 0.5f * z1.w);
#pragma unroll
            for (int i = 0; i < K_TOP; i++) {
                float d = S->delta[i];
                const float* base = &g_wbt[(size_t)S->didx[i] * TC];
                float4 w0 = *reinterpret_cast<const float4*>(&base[c0 * 4]);
                a0.x = fmaf(d, w0.x, a0.x); a0.y = fmaf(d, w0.y, a0.y);
                a0.z = fmaf(d, w0.z, a0.z); a0.w = fmaf(d, w0.w, a0.w);
                if (two) {
                    float4 w1 = *reinterpret_cast<const float4*>(&base[c1 * 4]);
                    a1.x = fmaf(d, w1.x, a1.x); a1.y = fmaf(d, w1.y, a1.y);
                    a1.z = fmaf(d, w1.z, a1.z); a1.w = fmaf(d, w1.w, a1.w);
                }
            }
            z0 = a0; z1 = a1;
        }

        // ---- phase A: winner cell + column max of pi + psi decay ----
#pragma unroll
        for (int h = 0; h < 2; h++) {
            int c = (h == 0) ? c0 : c1;
            if (h == 1 && !two) break;
            float4 z = (h == 0) ? z0 : z1;
            float  zac = (h == 0) ? zac0 : zac1;
            float4 ph  = *reinterpret_cast<const float4*>(&S->psi[c * 4]);
            float sig[4] = {zac + z.x, zac + z.y, zac + z.z, zac + z.w};
            float pv [4] = {sig[0] * (1.f - ph.x), sig[1] * (1.f - ph.y),
                            sig[2] * (1.f - ph.z), sig[3] * (1.f - ph.w)};
            float best = pv[0]; int bw = 0;
#pragma unroll
            for (int n = 1; n < N_CELLS; n++)
                if (pv[n] > best) { best = pv[n]; bw = n; }
            S->lam[c] = best;
            S->win[c] = (unsigned char)bw;
            S->sig[c] = sig[bw];
            *reinterpret_cast<float4*>(&S->psi[c * 4]) =
                make_float4(0.5f * ph.x, 0.5f * ph.y, 0.5f * ph.z, 0.5f * ph.w);
        }
        __syncthreads();

        // ---- top-K by warp 0 (R9 butterfly + tree rescan) ----
        if (warpid == 0) {
            float v[32];
#pragma unroll
            for (int j = 0; j < 32; j++) {
                int c = j * 32 + lane;
                v[j] = (c < M_COLS) ? S->lam[c] : -INFINITY;
            }
            float lv; int lj;
            tree_max32(v, lv, lj);
            int mycol = 0;

            for (int it = 0; it < K_TOP; it++) {
                float bv = lv;
                int   bc = lj * 32 + lane;
#pragma unroll
                for (int off = 16; off > 0; off >>= 1) {
                    float ov = __shfl_xor_sync(0xffffffffu, bv, off);
                    int   oc = __shfl_xor_sync(0xffffffffu, bc, off);
                    if (ov > bv || (ov == bv && oc < bc)) { bv = ov; bc = oc; }
                }
                if (lane == it) mycol = bc;
                if ((bc & 31) == lane) {
                    v[bc >> 5] = -INFINITY;
                    tree_max32(v, lv, lj);
                }
            }
            __syncwarp();

            // ---- emit: lanes 0..24, one winner each (psi already decayed) ----
            if (lane < K_TOP) {
                int   c    = mycol;
                int   w    = (int)S->win[c];
                int   cell = c * N_CELLS + w;
                float y    = tanhf(S->sig[c]);
                float pd   = S->psi[cell];
                S->didx [lane] = cell;
                S->delta[lane] = fmaxf(y - pd, 0.f);
                S->psi[cell]   = fmaxf(pd, y);
                size_t o = ((size_t)t * B_SZ + b) * K_TOP + lane;
                g_ycidx[o] = c;
                g_ycval[o] = fmaxf(y, 0.f);
            }
        }
        __syncthreads();
    }
}

// ---------------- fused GEMM + scan kernel (scan blocks FIRST) ----------------
__global__ void __launch_bounds__(512, 2)
fused_gemm_scan(const float* __restrict__ x, const float* __restrict__ w_a)
{
    __shared__ __align__(16) char smem[sizeof(GemmSmem)];
    if (blockIdx.x < B_SZ) scan_part(smem, blockIdx.x);
    else                   gemm_part(x, w_a, smem, blockIdx.x - B_SZ);
}

// ---------------- sparse decode: out[tb] = b_d + sum_i y_i * w_dT[c_i] ----------
__global__ void __launch_bounds__(256) decode_kernel(const float* __restrict__ b_d,
                                                     float* __restrict__ out)
{
    const int tb  = blockIdx.x;
    const int tid = threadIdx.x;

    __shared__ int   s_c[K_TOP];
    __shared__ float s_y[K_TOP];
    if (tid < K_TOP) {
        s_c[tid] = g_ycidx[(size_t)tb * K_TOP + tid];
        s_y[tid] = g_ycval[(size_t)tb * K_TOP + tid];
    }
    __syncthreads();

    float4 acc = *reinterpret_cast<const float4*>(&b_d[tid * 4]);
#pragma unroll
    for (int i = 0; i < K_TOP; i++) {
        float y = s_y[i];
        const float4 w = *reinterpret_cast<const float4*>(
            &g_wdt[(size_t)s_c[i] * D_OUT + tid * 4]);
        acc.x = fmaf(y, w.x, acc.x);
        acc.y = fmaf(y, w.y, acc.y);
        acc.z = fmaf(y, w.z, acc.z);
        acc.w = fmaf(y, w.w, acc.w);
    }
    *reinterpret_cast<float4*>(&out[(size_t)tb * D_OUT + tid * 4]) = acc;
}

// ---------------- host launch ----------------
extern "C" void kernel_launch(void* const* d_in, const int* in_sizes, int n_in,
                              void* d_out, int out_size)
{
    const float* x   = (const float*)d_in[0];   // [T, B, D_IN]
    const float* w_a = (const float*)d_in[1];   // [M, D_IN]
    const float* w_b = (const float*)d_in[2];   // [TC, TC]
    const float* w_d = (const float*)d_in[3];   // [D_OUT, M]
    const float* b_d = (const float*)d_in[4];   // [D_OUT]
    float* out = (float*)d_out;                 // [T, B, D_OUT]

    float *wbt, *wdt;
    cudaGetSymbolAddress((void**)&wbt, g_wbt);
    cudaGetSymbolAddress((void**)&wdt, g_wdt);

    zero_cnt_kernel<<<1, 64>>>();

    transpose_kernel<<<dim3(TC / 32, TC / 32), dim3(32, 8)>>>(w_b, wbt, TC, TC);
    transpose_kernel<<<dim3((M_COLS + 31) / 32, D_OUT / 32), dim3(32, 8)>>>(
        w_d, wdt, D_OUT, M_COLS);

    fused_gemm_scan<<<B_SZ + GEMM_BLOCKS, 512>>>(x, w_a);

    decode_kernel<<<T_STEPS * B_SZ, 256>>>(b_d, out);
}